// round 15
// baseline (speedup 1.0000x reference)
#include <cuda_runtime.h>
#include <cuda_bf16.h>
#include <math.h>
#include <stdint.h>

#define SEQ 4096
#define DM  2048
#define NH  16
#define DQK 128

typedef __nv_bfloat16 bf16;

// ---------------- single 128 MiB heap, phase-overlaid (audited in R10) ------
__device__ __align__(1024) unsigned char g_heap[134217728];
#define QOFF 0u
#define KOFF 33554432u
#define ZOFF 67108864u
#define WH   100663296u
#define WL   109051904u
#define VTH  100663296u
#define VTL  117440512u
#define OTH  0u
#define OTL  8388608u

// ---------------- helpers ---------------------------------------------------
__device__ __forceinline__ void mma16816(float* c, const uint32_t* a, const uint32_t* b) {
    asm volatile(
        "mma.sync.aligned.m16n8k16.row.col.f32.bf16.bf16.f32 "
        "{%0,%1,%2,%3}, {%4,%5,%6,%7}, {%8,%9}, {%0,%1,%2,%3};"
        : "+f"(c[0]), "+f"(c[1]), "+f"(c[2]), "+f"(c[3])
        : "r"(a[0]), "r"(a[1]), "r"(a[2]), "r"(a[3]), "r"(b[0]), "r"(b[1]));
}
__device__ __forceinline__ void ldsm4(uint32_t* r, uint32_t a) {
    asm volatile("ldmatrix.sync.aligned.m8n8.x4.shared.b16 {%0,%1,%2,%3}, [%4];"
                 : "=r"(r[0]), "=r"(r[1]), "=r"(r[2]), "=r"(r[3]) : "r"(a));
}
__device__ __forceinline__ uint32_t smem_u32(const void* p) {
    uint32_t a;
    asm("{ .reg .u64 t; cvta.to.shared.u64 t, %1; cvt.u32.u64 %0, t; }"
        : "=r"(a) : "l"(p));
    return a;
}
#define CPA16(dst, src) \
    asm volatile("cp.async.cg.shared.global [%0], [%1], 16;" :: "r"(dst), "l"(src))
#define CPA_COMMIT() asm volatile("cp.async.commit_group;" ::: "memory")
#define CPA_WAIT_ALL() asm volatile("cp.async.wait_all;" ::: "memory")
#define CPA_WAIT1() asm volatile("cp.async.wait_group 1;" ::: "memory")

__device__ __forceinline__ uint32_t pack_split(float a, float b, uint32_t& lopk) {
    bf16 ha = __float2bfloat16(a), hb = __float2bfloat16(b);
    bf16 la = __float2bfloat16(a - __bfloat162float(ha));
    bf16 lb = __float2bfloat16(b - __bfloat162float(hb));
    lopk = (uint32_t)__bfloat16_as_ushort(la) |
           ((uint32_t)__bfloat16_as_ushort(lb) << 16);
    return (uint32_t)__bfloat16_as_ushort(ha) |
           ((uint32_t)__bfloat16_as_ushort(hb) << 16);
}

// ---------------------------------------------------------------------------
// GEMM v9 = v7 (R12, proven) with PASS-MAJOR MMA ordering in the inner loop.
// 3-stage pipeline, one sync per chunk, wait_group 1.
// C[128,128] = A[128,K=2048] @ (Bh+Bl)[128rows][K]^T. 512 thr, 16 warps.
// Stage (40960 B): Ah +0, Al +10240, Bh +20480, Bl +30720 (80B row pitch).
// ---------------------------------------------------------------------------
__device__ __forceinline__ void gemm_v9(
    const float* __restrict__ A, int lda,
    const bf16* __restrict__ Bh, const bf16* __restrict__ Bl, int ldb,
    float* __restrict__ C, int ldc, float scale)
{
    __shared__ __align__(16) unsigned char sm[122880];
    const uint32_t sb = smem_u32(sm);

    const int t = threadIdx.x, lane = t & 31, wid = t >> 5;
    const int wm = (wid >> 3) * 64, wn = (wid & 7) * 16;

    const int arow = t >> 2, aseg = t & 3;
    const float* pA = A + (size_t)arow * lda + aseg * 8;
    const uint32_t asoff = arow * 80u + aseg * 16u;

    const int bt = t >> 8, brow = (t >> 1) & 127, bseg = t & 1;
    const char* pB = (const char*)((bt ? Bl : Bh) + (size_t)brow * ldb) + bseg * 32;
    const uint32_t bsoff = 20480u + bt * 10240u + brow * 80u + bseg * 32u;

    float acc[4][2][4];
#pragma unroll
    for (int i = 0; i < 4; i++)
#pragma unroll
        for (int j = 0; j < 2; j++)
#pragma unroll
            for (int r = 0; r < 4; r++) acc[i][j][r] = 0.0f;

    float a_f[8];
#define PREF_A(kc) do { \
        const float* ap_ = pA + (size_t)(kc) * 32; \
        float4 v0_ = *(const float4*)ap_; \
        float4 v1_ = *(const float4*)(ap_ + 4); \
        a_f[0] = v0_.x; a_f[1] = v0_.y; a_f[2] = v0_.z; a_f[3] = v0_.w; \
        a_f[4] = v1_.x; a_f[5] = v1_.y; a_f[6] = v1_.z; a_f[7] = v1_.w; \
    } while (0)
#define PACK_A(st) do { \
        uint32_t hi_[4], lo_[4]; \
        hi_[0] = pack_split(a_f[0], a_f[1], lo_[0]); \
        hi_[1] = pack_split(a_f[2], a_f[3], lo_[1]); \
        hi_[2] = pack_split(a_f[4], a_f[5], lo_[2]); \
        hi_[3] = pack_split(a_f[6], a_f[7], lo_[3]); \
        *(uint4*)(sm + (st) + asoff)         = make_uint4(hi_[0], hi_[1], hi_[2], hi_[3]); \
        *(uint4*)(sm + (st) + 10240 + asoff) = make_uint4(lo_[0], lo_[1], lo_[2], lo_[3]); \
    } while (0)
#define ISSUE_B(kc, st) do { \
        const char* src_ = pB + (size_t)(kc) * 64; \
        CPA16(sb + (st) + bsoff, src_); \
        CPA16(sb + (st) + bsoff + 16, src_ + 16); \
        CPA_COMMIT(); \
    } while (0)

    PREF_A(0); PACK_A(0u);      ISSUE_B(0, 0u);
    PREF_A(1); PACK_A(40960u);  ISSUE_B(1, 40960u);
    PREF_A(2);

    uint32_t cur = 0u, fill = 81920u;
    for (int kc = 0; kc < 64; kc++) {
        if (kc < 63) CPA_WAIT1();
        else         CPA_WAIT_ALL();
        __syncthreads();

        if (kc + 2 < 64) {
            PACK_A(fill);
            ISSUE_B(kc + 2, fill);
            if (kc + 3 < 64) PREF_A(kc + 3);
        }

#pragma unroll
        for (int ks = 0; ks < 2; ks++) {
            uint32_t ah[4][4], al[4][4], bh4[4], bl4[4];
            const uint32_t abase = sb + cur +
                (wm + (lane & 7) + ((lane >> 3) & 1) * 8) * 80 + ks * 32 + (lane >> 4) * 16;
#pragma unroll
            for (int i = 0; i < 4; i++) {
                ldsm4(ah[i], abase + i * 1280);
                ldsm4(al[i], abase + 10240 + i * 1280);
            }
            const uint32_t bbase = sb + cur + 20480 +
                (wn + (lane & 7) + ((lane >> 4) & 1) * 8) * 80 + ks * 32 + ((lane >> 3) & 1) * 16;
            ldsm4(bh4, bbase);
            ldsm4(bl4, bbase + 10240);
            // PASS-MAJOR: adjacent MMAs hit different accumulators
#pragma unroll
            for (int i = 0; i < 4; i++)
#pragma unroll
                for (int j = 0; j < 2; j++)
                    mma16816(acc[i][j], ah[i], &bh4[j * 2]);
#pragma unroll
            for (int i = 0; i < 4; i++)
#pragma unroll
                for (int j = 0; j < 2; j++)
                    mma16816(acc[i][j], al[i], &bh4[j * 2]);
#pragma unroll
            for (int i = 0; i < 4; i++)
#pragma unroll
                for (int j = 0; j < 2; j++)
                    mma16816(acc[i][j], ah[i], &bl4[j * 2]);
        }

        cur  = (cur  == 81920u) ? 0u : cur  + 40960u;
        fill = (fill == 81920u) ? 0u : fill + 40960u;
    }
#undef PREF_A
#undef PACK_A
#undef ISSUE_B

    const int g = lane >> 2, qq = lane & 3;
#pragma unroll
    for (int i = 0; i < 4; i++)
#pragma unroll
        for (int j = 0; j < 2; j++) {
            const int row = wm + i * 16 + g;
            const int col = wn + j * 8 + qq * 2;
            float2 lo = make_float2(acc[i][j][0] * scale, acc[i][j][1] * scale);
            float2 hi = make_float2(acc[i][j][2] * scale, acc[i][j][3] * scale);
            *(float2*)(C + (size_t)row * ldc + col)       = lo;
            *(float2*)(C + (size_t)(row + 8) * ldc + col) = hi;
        }
}

__global__ void __launch_bounds__(512) proj_v9(const float* __restrict__ x,
                                              unsigned dstoff)
{
    const int h = blockIdx.y;
    const bf16* bh = (const bf16*)(g_heap + WH) + (size_t)h * 262144;
    const bf16* bl = (const bf16*)(g_heap + WL) + (size_t)h * 262144;
    float* C = (float*)(g_heap + dstoff) +
               (size_t)h * SEQ * DQK + (size_t)blockIdx.x * 128 * DQK;
    gemm_v9(x + (size_t)blockIdx.x * 128 * DM, DM, bh, bl, DM, C, DQK, 1.0f);
}

__global__ void __launch_bounds__(512) outproj_v9(float* __restrict__ out)
{
    const float* z = (const float*)(g_heap + ZOFF);
    const bf16* bh = (const bf16*)(g_heap + OTH) + (size_t)blockIdx.y * 128 * 2048;
    const bf16* bl = (const bf16*)(g_heap + OTL) + (size_t)blockIdx.y * 128 * 2048;
    gemm_v9(z + (size_t)blockIdx.x * 128 * 2048, 2048, bh, bl, 2048,
            out + (size_t)blockIdx.x * 128 * DM + blockIdx.y * 128,
            DM, 4.8828125e-4f);
}

// ---------------------------------------------------------------------------
// prep kernels (R10-verbatim)
// ---------------------------------------------------------------------------
__global__ void __launch_bounds__(256) splitwT(const float* __restrict__ w)
{
    __shared__ float tile[32][33];
    const int h = blockIdx.z;
    const float* src = w + (size_t)h * 262144;
    bf16* oh = (bf16*)(g_heap + WH) + (size_t)h * 262144;
    bf16* ol = (bf16*)(g_heap + WL) + (size_t)h * 262144;
    const int tx = threadIdx.x, ty = threadIdx.y;
    const int k0 = blockIdx.x * 32, n0 = blockIdx.y * 32;
#pragma unroll
    for (int i = 0; i < 4; i++)
        tile[ty + 8 * i][tx] = src[(size_t)(k0 + ty + 8 * i) * 128 + n0 + tx];
    __syncthreads();
#pragma unroll
    for (int i = 0; i < 4; i++) {
        float v = tile[tx][ty + 8 * i];
        bf16 hh = __float2bfloat16(v);
        oh[(size_t)(n0 + ty + 8 * i) * 2048 + k0 + tx] = hh;
        ol[(size_t)(n0 + ty + 8 * i) * 2048 + k0 + tx] =
            __float2bfloat16(v - __bfloat162float(hh));
    }
}

__global__ void __launch_bounds__(256) osplitT(const float* __restrict__ o)
{
    __shared__ float tile[32][33];
    bf16* oh = (bf16*)(g_heap + OTH);
    bf16* ol = (bf16*)(g_heap + OTL);
    const int tx = threadIdx.x, ty = threadIdx.y;
    const int a0 = blockIdx.x * 32, d0 = blockIdx.y * 32;
#pragma unroll
    for (int i = 0; i < 4; i++)
        tile[ty + 8 * i][tx] = o[(size_t)(a0 + ty + 8 * i) * 2048 + d0 + tx];
    __syncthreads();
#pragma unroll
    for (int i = 0; i < 4; i++) {
        float v = tile[tx][ty + 8 * i];
        bf16 hh = __float2bfloat16(v);
        oh[(size_t)(d0 + ty + 8 * i) * 2048 + a0 + tx] = hh;
        ol[(size_t)(d0 + ty + 8 * i) * 2048 + a0 + tx] =
            __float2bfloat16(v - __bfloat162float(hh));
    }
}

__global__ void __launch_bounds__(256) rope_pack(const float* __restrict__ theta)
{
    const float tf = theta[0];
    const int s = blockIdx.x * 4 + (threadIdx.x >> 6);
    const int j = threadIdx.x & 63;
    const int h = blockIdx.y;
    char* base = (char*)g_heap + (blockIdx.z ? KOFF : QOFF) +
                 ((size_t)(h * 4096 + s)) * 512;
    float* rowp = (float*)base;

    const float x1 = rowp[j];
    const float x2 = rowp[j + 64];
    const float rate = tf * (-(float)j * 0.015625f);
    const float rot  = __fmul_rn((float)s, rate);
    float sv, cv;
    sincosf(rot, &sv, &cv);
    const float y1 = (cv * x1 - sv * x2) / 3.36358566101485845f;
    const float y2 = (sv * x1 + cv * x2) / 3.36358566101485845f;

    __syncthreads();

    bf16* hp = (bf16*)base;
    bf16 h1 = __float2bfloat16(y1);
    bf16 h2 = __float2bfloat16(y2);
    hp[j]            = h1;
    hp[j + 64]       = h2;
    hp[128 + j]      = __float2bfloat16(y1 - __bfloat162float(h1));
    hp[128 + j + 64] = __float2bfloat16(y2 - __bfloat162float(h2));
}

__global__ void __launch_bounds__(256) tspv()
{
    __shared__ float tile[32][33];
    const int h = blockIdx.z;
    const float* pv = (const float*)(g_heap + ZOFF) + (size_t)h * 4096 * 128;
    bf16* vh = (bf16*)(g_heap + VTH) + (size_t)h * 128 * 4096;
    bf16* vl = (bf16*)(g_heap + VTL) + (size_t)h * 128 * 4096;
    const int tx = threadIdx.x, ty = threadIdx.y;
    const int s0 = blockIdx.x * 32, v0 = blockIdx.y * 32;
#pragma unroll
    for (int i = 0; i < 4; i++)
        tile[ty + 8 * i][tx] = pv[(size_t)(s0 + ty + 8 * i) * 128 + v0 + tx];
    __syncthreads();
#pragma unroll
    for (int i = 0; i < 4; i++) {
        float v = tile[tx][ty + 8 * i];
        bf16 hh = __float2bfloat16(v);
        vh[(size_t)(v0 + ty + 8 * i) * 4096 + s0 + tx] = hh;
        vl[(size_t)(v0 + ty + 8 * i) * 4096 + s0 + tx] =
            __float2bfloat16(v - __bfloat162float(hh));
    }
}

// ---------------------------------------------------------------------------
// Flash attention: R12 core with pass-major MMA ordering in QK and PV.
// ---------------------------------------------------------------------------
#define AQH 0u
#define AQL 34816u
#define ABUF 69632u
#define BUFSZ 71680u
#define BKH 0u
#define BKL 17408u
#define BVH 34816u
#define BVL 53248u

__global__ void __launch_bounds__(256) attn_hmma()
{
    extern __shared__ char smem[];
    const uint32_t sb = smem_u32(smem);
    const int t = threadIdx.x, lane = t & 31, wid = t >> 5;
    const int g = lane >> 2, qq = lane & 3;
    const int bx = blockIdx.x;
    const int qt = 31 - (bx >> 4);
    const int h  = bx & 15;
    const int r0 = qt * 128;
    const int jmax = 2 * qt + 1;

    const char* qbase = (const char*)g_heap + QOFF + ((size_t)(h * 4096 + r0)) * 512;
    const char* kbase = (const char*)g_heap + KOFF + ((size_t)h * 4096) * 512;

    {
        const char* src = qbase + (size_t)(t & 127) * 512 + (t >> 7) * 256;
        const uint32_t dst = sb + ((t >> 7) ? AQL : AQH) + (t & 127) * 272;
#pragma unroll
        for (int u = 0; u < 16; u++) CPA16(dst + u * 16, src + u * 16);
    }
    const int krow = t & 63, kseg = (t >> 6) & 1, kha = t >> 7;
    const int vrow = t & 127, vha = t >> 7;
    const char* vsrc0 = (const char*)g_heap + (vha ? VTL : VTH) +
                        ((size_t)h * 128 + vrow) * 8192;
    {
        const char* ksrc = kbase + (size_t)krow * 512 + kha * 256 + kseg * 128;
        const uint32_t kdst = sb + ABUF + (kha ? BKL : BKH) + krow * 272 + kseg * 128;
#pragma unroll
        for (int u = 0; u < 8; u++) CPA16(kdst + u * 16, ksrc + u * 16);
        const uint32_t vdst = sb + ABUF + (vha ? BVL : BVH) + vrow * 144;
#pragma unroll
        for (int u = 0; u < 8; u++) CPA16(vdst + u * 16, vsrc0 + u * 16);
    }
    CPA_COMMIT();

    CPA_WAIT_ALL();
    __syncthreads();
    uint32_t qfh[8][4], qfl[8][4];
#pragma unroll
    for (int ks = 0; ks < 8; ks++) {
        const uint32_t qa = sb + AQH +
            (wid * 16 + (lane & 7) + ((lane >> 3) & 1) * 8) * 272 +
            ks * 32 + (lane >> 4) * 16;
        ldsm4(qfh[ks], qa);
        ldsm4(qfl[ks], qa + 34816);
    }

    float zacc[16][4];
#pragma unroll
    for (int n = 0; n < 16; n++)
#pragma unroll
        for (int r = 0; r < 4; r++) zacc[n][r] = 0.0f;
    float m0 = -3e38f, m1 = -3e38f, l0 = 0.0f, l1 = 0.0f;

    for (int j = 0; j <= jmax; j++) {
        const int b = j & 1;
        const uint32_t sbuf = sb + ABUF + b * BUFSZ;
        CPA_WAIT_ALL();
        __syncthreads();

        if (j < jmax) {
            const int col1 = (j + 1) * 64;
            const uint32_t ob = sb + ABUF + (b ^ 1) * BUFSZ;
            const char* ksrc = kbase + (size_t)(col1 + krow) * 512 + kha * 256 + kseg * 128;
            const uint32_t kdst = ob + (kha ? BKL : BKH) + krow * 272 + kseg * 128;
#pragma unroll
            for (int u = 0; u < 8; u++) CPA16(kdst + u * 16, ksrc + u * 16);
            const char* vsrc = vsrc0 + col1 * 2;
            const uint32_t vdst = ob + (vha ? BVL : BVH) + vrow * 144;
#pragma unroll
            for (int u = 0; u < 8; u++) CPA16(vdst + u * 16, vsrc + u * 16);
            CPA_COMMIT();
        }

        float sacc[8][4];
#pragma unroll
        for (int n = 0; n < 8; n++)
#pragma unroll
            for (int r = 0; r < 4; r++) sacc[n][r] = 0.0f;

        // ---- S = Q @ K^T : pass-major per ks ----
#pragma unroll
        for (int ks = 0; ks < 8; ks++) {
            uint32_t kh[4][4], kl[4][4];
#pragma unroll
            for (int n2 = 0; n2 < 4; n2++) {
                const uint32_t ka = sbuf + BKH +
                    (n2 * 16 + (lane & 7) + ((lane >> 4) & 1) * 8) * 272 +
                    ks * 32 + ((lane >> 3) & 1) * 16;
                ldsm4(kh[n2], ka);
                ldsm4(kl[n2], ka + 17408);
            }
#pragma unroll
            for (int n2 = 0; n2 < 4; n2++)
#pragma unroll
                for (int bb = 0; bb < 2; bb++)
                    mma16816(sacc[2 * n2 + bb], qfh[ks], &kh[n2][bb * 2]);
#pragma unroll
            for (int n2 = 0; n2 < 4; n2++)
#pragma unroll
                for (int bb = 0; bb < 2; bb++)
                    mma16816(sacc[2 * n2 + bb], qfl[ks], &kh[n2][bb * 2]);
#pragma unroll
            for (int n2 = 0; n2 < 4; n2++)
#pragma unroll
                for (int bb = 0; bb < 2; bb++)
                    mma16816(sacc[2 * n2 + bb], qfh[ks], &kl[n2][bb * 2]);
        }

        if (j >= 2 * qt) {
            const int rowlo = r0 + wid * 16 + g;
            const int colb  = j * 64 + qq * 2;
#pragma unroll
            for (int n = 0; n < 8; n++) {
                const int c0 = colb + n * 8, c1 = c0 + 1;
                if (c0 > rowlo)     sacc[n][0] = -1e30f;
                if (c1 > rowlo)     sacc[n][1] = -1e30f;
                if (c0 > rowlo + 8) sacc[n][2] = -1e30f;
                if (c1 > rowlo + 8) sacc[n][3] = -1e30f;
            }
        }

        float rm0 = -3e38f, rm1 = -3e38f;
#pragma unroll
        for (int n = 0; n < 8; n++) {
            rm0 = fmaxf(rm0, fmaxf(sacc[n][0], sacc[n][1]));
            rm1 = fmaxf(rm1, fmaxf(sacc[n][2], sacc[n][3]));
        }
        rm0 = fmaxf(rm0, __shfl_xor_sync(0xffffffffu, rm0, 1));
        rm0 = fmaxf(rm0, __shfl_xor_sync(0xffffffffu, rm0, 2));
        rm1 = fmaxf(rm1, __shfl_xor_sync(0xffffffffu, rm1, 1));
        rm1 = fmaxf(rm1, __shfl_xor_sync(0xffffffffu, rm1, 2));
        const float mn0 = fmaxf(m0, rm0), mn1 = fmaxf(m1, rm1);
        const float al0 = __expf(m0 - mn0), al1 = __expf(m1 - mn1);
        m0 = mn0; m1 = mn1;

        float rs0 = 0.0f, rs1 = 0.0f;
#pragma unroll
        for (int n = 0; n < 8; n++) {
            sacc[n][0] = __expf(sacc[n][0] - mn0);
            sacc[n][1] = __expf(sacc[n][1] - mn0);
            sacc[n][2] = __expf(sacc[n][2] - mn1);
            sacc[n][3] = __expf(sacc[n][3] - mn1);
            rs0 += sacc[n][0] + sacc[n][1];
            rs1 += sacc[n][2] + sacc[n][3];
        }
        rs0 += __shfl_xor_sync(0xffffffffu, rs0, 1);
        rs0 += __shfl_xor_sync(0xffffffffu, rs0, 2);
        rs1 += __shfl_xor_sync(0xffffffffu, rs1, 1);
        rs1 += __shfl_xor_sync(0xffffffffu, rs1, 2);
        l0 = l0 * al0 + rs0;
        l1 = l1 * al1 + rs1;

#pragma unroll
        for (int n = 0; n < 16; n++) {
            zacc[n][0] *= al0; zacc[n][1] *= al0;
            zacc[n][2] *= al1; zacc[n][3] *= al1;
        }

        uint32_t pa_h[4][4], pa_l[4][4];
#pragma unroll
        for (int kt = 0; kt < 4; kt++) {
            pa_h[kt][0] = pack_split(sacc[2*kt][0],   sacc[2*kt][1],   pa_l[kt][0]);
            pa_h[kt][1] = pack_split(sacc[2*kt][2],   sacc[2*kt][3],   pa_l[kt][1]);
            pa_h[kt][2] = pack_split(sacc[2*kt+1][0], sacc[2*kt+1][1], pa_l[kt][2]);
            pa_h[kt][3] = pack_split(sacc[2*kt+1][2], sacc[2*kt+1][3], pa_l[kt][3]);
        }

        // ---- Z += P @ V : pass-major per (kt, n-half) ----
#pragma unroll
        for (int kt = 0; kt < 4; kt++) {
#pragma unroll
            for (int h2 = 0; h2 < 2; h2++) {
                uint32_t vh[4][4], vl[4][4];
#pragma unroll
                for (int q4 = 0; q4 < 4; q4++) {
                    const int n2 = h2 * 4 + q4;
                    const uint32_t va = sbuf + BVH +
                        (n2 * 16 + (lane & 7) + ((lane >> 4) & 1) * 8) * 144 +
                        kt * 32 + ((lane >> 3) & 1) * 16;
                    ldsm4(vh[q4], va);
                    ldsm4(vl[q4], va + 18432);
                }
#pragma unroll
                for (int q4 = 0; q4 < 4; q4++)
#pragma unroll
                    for (int bb = 0; bb < 2; bb++)
                        mma16816(zacc[2 * (h2 * 4 + q4) + bb], pa_h[kt], &vh[q4][bb * 2]);
#pragma unroll
                for (int q4 = 0; q4 < 4; q4++)
#pragma unroll
                    for (int bb = 0; bb < 2; bb++)
                        mma16816(zacc[2 * (h2 * 4 + q4) + bb], pa_l[kt], &vh[q4][bb * 2]);
#pragma unroll
                for (int q4 = 0; q4 < 4; q4++)
#pragma unroll
                    for (int bb = 0; bb < 2; bb++)
                        mma16816(zacc[2 * (h2 * 4 + q4) + bb], pa_h[kt], &vl[q4][bb * 2]);
            }
        }
        __syncthreads();
    }

    const float i0 = 1.0f / l0, i1 = 1.0f / l1;
    float* zp = (float*)(g_heap + ZOFF);
    const int rowlo = r0 + wid * 16 + g;
#pragma unroll
    for (int n = 0; n < 16; n++) {
        const int col = h * 128 + n * 8 + qq * 2;
        *(float2*)(zp + (size_t)rowlo * 2048 + col) =
            make_float2(zacc[n][0] * i0, zacc[n][1] * i0);
        *(float2*)(zp + (size_t)(rowlo + 8) * 2048 + col) =
            make_float2(zacc[n][2] * i1, zacc[n][3] * i1);
    }
}

// ---------------------------------------------------------------------------
extern "C" void kernel_launch(void* const* d_in, const int* in_sizes, int n_in,
                              void* d_out, int out_size)
{
    const float* x     = (const float*)d_in[0];
    const float* q     = (const float*)d_in[1];
    const float* k     = (const float*)d_in[2];
    const float* v     = (const float*)d_in[3];
    const float* o     = (const float*)d_in[4];
    const float* theta = (const float*)d_in[5];
    float* out = (float*)d_out;

    cudaFuncSetAttribute(attn_hmma,
                         cudaFuncAttributeMaxDynamicSharedMemorySize, 212992);

    splitwT<<<dim3(64, 4, 16), dim3(32, 8)>>>(q);
    proj_v9<<<dim3(32, 16), 512>>>(x, QOFF);
    splitwT<<<dim3(64, 4, 16), dim3(32, 8)>>>(k);
    proj_v9<<<dim3(32, 16), 512>>>(x, KOFF);
    splitwT<<<dim3(64, 4, 16), dim3(32, 8)>>>(v);
    proj_v9<<<dim3(32, 16), 512>>>(x, ZOFF);
    rope_pack<<<dim3(1024, 16, 2), 256>>>(theta);
    tspv<<<dim3(128, 4, 16), dim3(32, 8)>>>();
    attn_hmma<<<512, 256, 212992>>>();
    osplitT<<<dim3(64, 64), dim3(32, 8)>>>(o);
    outproj_v9<<<dim3(32, 16), 512>>>(out);
}

// round 16
// speedup vs baseline: 1.1074x; 1.1074x over previous
#include <cuda_runtime.h>
#include <cuda_bf16.h>
#include <cuda_fp16.h>
#include <math.h>
#include <stdint.h>

#define SEQ 4096
#define DM  2048
#define NH  16
#define DQK 128

typedef __nv_bfloat16 bf16;

// ---------------- single 128 MiB heap, phase-overlaid (re-audited R16) ------
// [0,32M)    Q fp32 proj -> rope-packed bf16 hi|lo rows (512 B/row)
// [32,64M)   K same
// [64,80M)   x16 hi (vproj A) -> after vproj dead -> z16 hi (attn out)
// [80,96M)   x16 lo            ->                    z16 lo
// [96,112M)  vT fp16 [h][v][s]
// [112,128M) W bf16 split scratch (8M hi + 8M lo, rewritten per q/k)
__device__ __align__(1024) unsigned char g_heap[134217728];
#define QOFF 0u
#define KOFF 33554432u
#define XH16 67108864u
#define XL16 83886080u
#define ZH16 67108864u
#define ZL16 83886080u
#define VT16 100663296u
#define WH   117440512u
#define WL   125829120u

// ---------------- helpers ---------------------------------------------------
__device__ __forceinline__ void mma16816(float* c, const uint32_t* a, const uint32_t* b) {
    asm volatile(
        "mma.sync.aligned.m16n8k16.row.col.f32.bf16.bf16.f32 "
        "{%0,%1,%2,%3}, {%4,%5,%6,%7}, {%8,%9}, {%0,%1,%2,%3};"
        : "+f"(c[0]), "+f"(c[1]), "+f"(c[2]), "+f"(c[3])
        : "r"(a[0]), "r"(a[1]), "r"(a[2]), "r"(a[3]), "r"(b[0]), "r"(b[1]));
}
__device__ __forceinline__ void mma_f16(float* c, const uint32_t* a, const uint32_t* b) {
    asm volatile(
        "mma.sync.aligned.m16n8k16.row.col.f32.f16.f16.f32 "
        "{%0,%1,%2,%3}, {%4,%5,%6,%7}, {%8,%9}, {%0,%1,%2,%3};"
        : "+f"(c[0]), "+f"(c[1]), "+f"(c[2]), "+f"(c[3])
        : "r"(a[0]), "r"(a[1]), "r"(a[2]), "r"(a[3]), "r"(b[0]), "r"(b[1]));
}
__device__ __forceinline__ void ldsm4(uint32_t* r, uint32_t a) {
    asm volatile("ldmatrix.sync.aligned.m8n8.x4.shared.b16 {%0,%1,%2,%3}, [%4];"
                 : "=r"(r[0]), "=r"(r[1]), "=r"(r[2]), "=r"(r[3]) : "r"(a));
}
__device__ __forceinline__ uint32_t smem_u32(const void* p) {
    uint32_t a;
    asm("{ .reg .u64 t; cvta.to.shared.u64 t, %1; cvt.u32.u64 %0, t; }"
        : "=r"(a) : "l"(p));
    return a;
}
#define CPA16(dst, src) \
    asm volatile("cp.async.cg.shared.global [%0], [%1], 16;" :: "r"(dst), "l"(src))
#define CPA_COMMIT() asm volatile("cp.async.commit_group;" ::: "memory")
#define CPA_WAIT_ALL() asm volatile("cp.async.wait_all;" ::: "memory")
#define CPA_WAIT1() asm volatile("cp.async.wait_group 1;" ::: "memory")

__device__ __forceinline__ uint32_t pack_split(float a, float b, uint32_t& lopk) {
    bf16 ha = __float2bfloat16(a), hb = __float2bfloat16(b);
    bf16 la = __float2bfloat16(a - __bfloat162float(ha));
    bf16 lb = __float2bfloat16(b - __bfloat162float(hb));
    lopk = (uint32_t)__bfloat16_as_ushort(la) |
           ((uint32_t)__bfloat16_as_ushort(lb) << 16);
    return (uint32_t)__bfloat16_as_ushort(ha) |
           ((uint32_t)__bfloat16_as_ushort(hb) << 16);
}
__device__ __forceinline__ uint32_t pack_split16(float a, float b, uint32_t& lopk) {
    __half ha = __float2half_rn(a), hb = __float2half_rn(b);
    __half la = __float2half_rn(a - __half2float(ha));
    __half lb = __float2half_rn(b - __half2float(hb));
    lopk = (uint32_t)__half_as_ushort(la) | ((uint32_t)__half_as_ushort(lb) << 16);
    return (uint32_t)__half_as_ushort(ha) | ((uint32_t)__half_as_ushort(hb) << 16);
}

// ---------------------------------------------------------------------------
// GEMM v9 (R14-proven, bf16 3-pass) for Q/K projections. Unchanged.
// ---------------------------------------------------------------------------
__device__ __forceinline__ void gemm_v9(
    const float* __restrict__ A, int lda,
    const bf16* __restrict__ Bh, const bf16* __restrict__ Bl, int ldb,
    float* __restrict__ C, int ldc, float scale)
{
    __shared__ __align__(16) unsigned char sm[122880];
    const uint32_t sb = smem_u32(sm);

    const int t = threadIdx.x, lane = t & 31, wid = t >> 5;
    const int wm = (wid >> 3) * 64, wn = (wid & 7) * 16;

    const int arow = t >> 2, aseg = t & 3;
    const float* pA = A + (size_t)arow * lda + aseg * 8;
    const uint32_t asoff = arow * 80u + aseg * 16u;

    const int bt = t >> 8, brow = (t >> 1) & 127, bseg = t & 1;
    const char* pB = (const char*)((bt ? Bl : Bh) + (size_t)brow * ldb) + bseg * 32;
    const uint32_t bsoff = 20480u + bt * 10240u + brow * 80u + bseg * 32u;

    float acc[4][2][4];
#pragma unroll
    for (int i = 0; i < 4; i++)
#pragma unroll
        for (int j = 0; j < 2; j++)
#pragma unroll
            for (int r = 0; r < 4; r++) acc[i][j][r] = 0.0f;

    float a_f[8];
#define PREF_A(kc) do { \
        const float* ap_ = pA + (size_t)(kc) * 32; \
        float4 v0_ = *(const float4*)ap_; \
        float4 v1_ = *(const float4*)(ap_ + 4); \
        a_f[0] = v0_.x; a_f[1] = v0_.y; a_f[2] = v0_.z; a_f[3] = v0_.w; \
        a_f[4] = v1_.x; a_f[5] = v1_.y; a_f[6] = v1_.z; a_f[7] = v1_.w; \
    } while (0)
#define PACK_A(st) do { \
        uint32_t hi_[4], lo_[4]; \
        hi_[0] = pack_split(a_f[0], a_f[1], lo_[0]); \
        hi_[1] = pack_split(a_f[2], a_f[3], lo_[1]); \
        hi_[2] = pack_split(a_f[4], a_f[5], lo_[2]); \
        hi_[3] = pack_split(a_f[6], a_f[7], lo_[3]); \
        *(uint4*)(sm + (st) + asoff)         = make_uint4(hi_[0], hi_[1], hi_[2], hi_[3]); \
        *(uint4*)(sm + (st) + 10240 + asoff) = make_uint4(lo_[0], lo_[1], lo_[2], lo_[3]); \
    } while (0)
#define ISSUE_B(kc, st) do { \
        const char* src_ = pB + (size_t)(kc) * 64; \
        CPA16(sb + (st) + bsoff, src_); \
        CPA16(sb + (st) + bsoff + 16, src_ + 16); \
        CPA_COMMIT(); \
    } while (0)

    PREF_A(0); PACK_A(0u);      ISSUE_B(0, 0u);
    PREF_A(1); PACK_A(40960u);  ISSUE_B(1, 40960u);
    PREF_A(2);

    uint32_t cur = 0u, fill = 81920u;
    for (int kc = 0; kc < 64; kc++) {
        if (kc < 63) CPA_WAIT1();
        else         CPA_WAIT_ALL();
        __syncthreads();

        if (kc + 2 < 64) {
            PACK_A(fill);
            ISSUE_B(kc + 2, fill);
            if (kc + 3 < 64) PREF_A(kc + 3);
        }

#pragma unroll
        for (int ks = 0; ks < 2; ks++) {
            uint32_t ah[4][4], al[4][4], bh4[4], bl4[4];
            const uint32_t abase = sb + cur +
                (wm + (lane & 7) + ((lane >> 3) & 1) * 8) * 80 + ks * 32 + (lane >> 4) * 16;
#pragma unroll
            for (int i = 0; i < 4; i++) {
                ldsm4(ah[i], abase + i * 1280);
                ldsm4(al[i], abase + 10240 + i * 1280);
            }
            const uint32_t bbase = sb + cur + 20480 +
                (wn + (lane & 7) + ((lane >> 4) & 1) * 8) * 80 + ks * 32 + ((lane >> 3) & 1) * 16;
            ldsm4(bh4, bbase);
            ldsm4(bl4, bbase + 10240);
#pragma unroll
            for (int i = 0; i < 4; i++)
#pragma unroll
                for (int j = 0; j < 2; j++)
                    mma16816(acc[i][j], ah[i], &bh4[j * 2]);
#pragma unroll
            for (int i = 0; i < 4; i++)
#pragma unroll
                for (int j = 0; j < 2; j++)
                    mma16816(acc[i][j], al[i], &bh4[j * 2]);
#pragma unroll
            for (int i = 0; i < 4; i++)
#pragma unroll
                for (int j = 0; j < 2; j++)
                    mma16816(acc[i][j], ah[i], &bl4[j * 2]);
        }

        cur  = (cur  == 81920u) ? 0u : cur  + 40960u;
        fill = (fill == 81920u) ? 0u : fill + 40960u;
    }
#undef PREF_A
#undef PACK_A
#undef ISSUE_B

    const int g = lane >> 2, qq = lane & 3;
#pragma unroll
    for (int i = 0; i < 4; i++)
#pragma unroll
        for (int j = 0; j < 2; j++) {
            const int row = wm + i * 16 + g;
            const int col = wn + j * 8 + qq * 2;
            float2 lo = make_float2(acc[i][j][0] * scale, acc[i][j][1] * scale);
            float2 hi = make_float2(acc[i][j][2] * scale, acc[i][j][3] * scale);
            *(float2*)(C + (size_t)row * ldc + col)       = lo;
            *(float2*)(C + (size_t)(row + 8) * ldc + col) = hi;
        }
}

__global__ void __launch_bounds__(512) proj_v9(const float* __restrict__ x,
                                              unsigned dstoff)
{
    const int h = blockIdx.y;
    const bf16* bh = (const bf16*)(g_heap + WH) + (size_t)h * 262144;
    const bf16* bl = (const bf16*)(g_heap + WL) + (size_t)h * 262144;
    float* C = (float*)(g_heap + dstoff) +
               (size_t)h * SEQ * DQK + (size_t)blockIdx.x * 128 * DQK;
    gemm_v9(x + (size_t)blockIdx.x * 128 * DM, DM, bh, bl, DM, C, DQK, 1.0f);
}

// ---------------------------------------------------------------------------
// GEMM 2-pass fp16: A = pre-split fp16 hi/lo (cp.async), B = fp32 [k][n]
// (n contiguous) cvt to fp16 in-loader. 512 thr, 16 warps, k-chunk 32.
// Stage (30720 B): Ah +0, Al +10240, B16 +20480 (80 B row pitch).
// mode 0: scaled fp32 C write. mode 1: transposed fp16 scatter (vT).
// ldsm/mma addressing identical to the proven v9 mapping.
// ---------------------------------------------------------------------------
__device__ __forceinline__ void gemm_2p(
    const __half* __restrict__ Ah, const __half* __restrict__ Al, int lda,
    const float* __restrict__ Bf, int ldbn,
    int mode, float* __restrict__ Cf, int ldc, float scale,
    __half* __restrict__ vtb, int s0)
{
    __shared__ __align__(16) unsigned char sm[61440];
    const uint32_t sb = smem_u32(sm);

    const int t = threadIdx.x, lane = t & 31, wid = t >> 5;
    const int wm = (wid >> 3) * 64, wn = (wid & 7) * 16;

    const int arow = t >> 2, aseg = t & 3;
    const char* pAh = (const char*)(Ah + (size_t)arow * lda) + aseg * 16;
    const char* pAl = (const char*)(Al + (size_t)arow * lda) + aseg * 16;
    const uint32_t asoff = arow * 80u + aseg * 16u;

    const int kp = t >> 5, nb = (t & 31) * 4;
    const float* pB0 = Bf + (size_t)(2 * kp) * ldbn + nb;
    const float* pB1 = pB0 + ldbn;

    float acc[4][2][4];
#pragma unroll
    for (int i = 0; i < 4; i++)
#pragma unroll
        for (int j = 0; j < 2; j++)
#pragma unroll
            for (int r = 0; r < 4; r++) acc[i][j][r] = 0.0f;

    float b_f[8];
#define PREF_B(kc) do { \
        const float* b0_ = pB0 + (size_t)(kc) * 32 * ldbn; \
        const float* b1_ = pB1 + (size_t)(kc) * 32 * ldbn; \
        float4 v0_ = *(const float4*)b0_; \
        float4 v1_ = *(const float4*)b1_; \
        b_f[0] = v0_.x; b_f[1] = v0_.y; b_f[2] = v0_.z; b_f[3] = v0_.w; \
        b_f[4] = v1_.x; b_f[5] = v1_.y; b_f[6] = v1_.z; b_f[7] = v1_.w; \
    } while (0)
#define ISSUE_A(kc, st) do { \
        CPA16(sb + (st) + asoff,         pAh + (size_t)(kc) * 64); \
        CPA16(sb + (st) + 10240 + asoff, pAl + (size_t)(kc) * 64); \
        CPA_COMMIT(); \
    } while (0)

    PREF_B(0);
    ISSUE_A(0, 0u);

    for (int kc = 0; kc < 64; kc++) {
        const uint32_t st = (kc & 1) * 30720u;
        __syncthreads();
        {
            uint32_t* bs = (uint32_t*)(sm + st + 20480);
#pragma unroll
            for (int i = 0; i < 4; i++) {
                __half2 w = __floats2half2_rn(b_f[i], b_f[4 + i]);
                bs[(nb + i) * 20 + kp] = *(uint32_t*)&w;
            }
        }
        if (kc < 63) {
            ISSUE_A(kc + 1, st ^ 30720u);
            PREF_B(kc + 1);
            CPA_WAIT1();
        } else {
            CPA_WAIT_ALL();
        }
        __syncthreads();

#pragma unroll
        for (int ks = 0; ks < 2; ks++) {
            uint32_t ah[4][4], al[4][4], b4[4];
            const uint32_t abase = sb + st +
                (wm + (lane & 7) + ((lane >> 3) & 1) * 8) * 80 + ks * 32 + (lane >> 4) * 16;
#pragma unroll
            for (int i = 0; i < 4; i++) {
                ldsm4(ah[i], abase + i * 1280);
                ldsm4(al[i], abase + 10240 + i * 1280);
            }
            const uint32_t bbase = sb + st + 20480 +
                (wn + (lane & 7) + ((lane >> 4) & 1) * 8) * 80 + ks * 32 + ((lane >> 3) & 1) * 16;
            ldsm4(b4, bbase);
#pragma unroll
            for (int i = 0; i < 4; i++)
#pragma unroll
                for (int j = 0; j < 2; j++)
                    mma_f16(acc[i][j], ah[i], &b4[j * 2]);
#pragma unroll
            for (int i = 0; i < 4; i++)
#pragma unroll
                for (int j = 0; j < 2; j++)
                    mma_f16(acc[i][j], al[i], &b4[j * 2]);
        }
    }
#undef PREF_B
#undef ISSUE_A

    const int g = lane >> 2, qq = lane & 3;
    if (mode == 0) {
#pragma unroll
        for (int i = 0; i < 4; i++)
#pragma unroll
            for (int j = 0; j < 2; j++) {
                const int row = wm + i * 16 + g;
                const int col = wn + j * 8 + qq * 2;
                float2 lo = make_float2(acc[i][j][0] * scale, acc[i][j][1] * scale);
                float2 hi = make_float2(acc[i][j][2] * scale, acc[i][j][3] * scale);
                *(float2*)(Cf + (size_t)row * ldc + col)       = lo;
                *(float2*)(Cf + (size_t)(row + 8) * ldc + col) = hi;
            }
    } else {
#pragma unroll
        for (int i = 0; i < 4; i++)
#pragma unroll
            for (int j = 0; j < 2; j++) {
                const int row = wm + i * 16 + g;
                const int col = wn + j * 8 + qq * 2;
                vtb[(size_t)col * 4096 + s0 + row]           = __float2half_rn(acc[i][j][0]);
                vtb[(size_t)(col + 1) * 4096 + s0 + row]     = __float2half_rn(acc[i][j][1]);
                vtb[(size_t)col * 4096 + s0 + row + 8]       = __float2half_rn(acc[i][j][2]);
                vtb[(size_t)(col + 1) * 4096 + s0 + row + 8] = __float2half_rn(acc[i][j][3]);
            }
    }
}

__global__ void __launch_bounds__(512) vproj16(const float* __restrict__ v)
{
    const int h = blockIdx.y;
    gemm_2p((const __half*)(g_heap + XH16) + (size_t)blockIdx.x * 128 * DM,
            (const __half*)(g_heap + XL16) + (size_t)blockIdx.x * 128 * DM, DM,
            v + (size_t)h * DM * DQK, DQK,
            1, 0, 0, 0.0f,
            (__half*)(g_heap + VT16) + (size_t)h * 128 * 4096, blockIdx.x * 128);
}

__global__ void __launch_bounds__(512) outproj16(float* __restrict__ out,
                                                const float* __restrict__ o)
{
    gemm_2p((const __half*)(g_heap + ZH16) + (size_t)blockIdx.x * 128 * 2048,
            (const __half*)(g_heap + ZL16) + (size_t)blockIdx.x * 128 * 2048, 2048,
            o + blockIdx.y * 128, 2048,
            0, out + (size_t)blockIdx.x * 128 * DM + blockIdx.y * 128, DM,
            4.8828125e-4f, 0, 0);
}

// ---------------------------------------------------------------------------
// prep kernels
// ---------------------------------------------------------------------------
__global__ void __launch_bounds__(256) splitwT(const float* __restrict__ w)
{
    __shared__ float tile[32][33];
    const int h = blockIdx.z;
    const float* src = w + (size_t)h * 262144;
    bf16* oh = (bf16*)(g_heap + WH) + (size_t)h * 262144;
    bf16* ol = (bf16*)(g_heap + WL) + (size_t)h * 262144;
    const int tx = threadIdx.x, ty = threadIdx.y;
    const int k0 = blockIdx.x * 32, n0 = blockIdx.y * 32;
#pragma unroll
    for (int i = 0; i < 4; i++)
        tile[ty + 8 * i][tx] = src[(size_t)(k0 + ty + 8 * i) * 128 + n0 + tx];
    __syncthreads();
#pragma unroll
    for (int i = 0; i < 4; i++) {
        float v = tile[tx][ty + 8 * i];
        bf16 hh = __float2bfloat16(v);
        oh[(size_t)(n0 + ty + 8 * i) * 2048 + k0 + tx] = hh;
        ol[(size_t)(n0 + ty + 8 * i) * 2048 + k0 + tx] =
            __float2bfloat16(v - __bfloat162float(hh));
    }
}

__global__ void __launch_bounds__(256) cvtx16s(const float* __restrict__ x)
{
    const size_t i = ((size_t)blockIdx.x * 256 + threadIdx.x) * 4;
    float4 vv = *(const float4*)(x + i);
    uint32_t hi0, hi1, lo0, lo1;
    hi0 = pack_split16(vv.x, vv.y, lo0);
    hi1 = pack_split16(vv.z, vv.w, lo1);
    *(uint2*)((__half*)(g_heap + XH16) + i) = make_uint2(hi0, hi1);
    *(uint2*)((__half*)(g_heap + XL16) + i) = make_uint2(lo0, lo1);
}

__global__ void __launch_bounds__(256) rope_pack(const float* __restrict__ theta)
{
    const float tf = theta[0];
    const int s = blockIdx.x * 4 + (threadIdx.x >> 6);
    const int j = threadIdx.x & 63;
    const int h = blockIdx.y;
    char* base = (char*)g_heap + (blockIdx.z ? KOFF : QOFF) +
                 ((size_t)(h * 4096 + s)) * 512;
    float* rowp = (float*)base;

    const float x1 = rowp[j];
    const float x2 = rowp[j + 64];
    const float rate = tf * (-(float)j * 0.015625f);
    const float rot  = __fmul_rn((float)s, rate);
    float sv, cv;
    sincosf(rot, &sv, &cv);
    const float y1 = (cv * x1 - sv * x2) / 3.36358566101485845f;
    const float y2 = (sv * x1 + cv * x2) / 3.36358566101485845f;

    __syncthreads();

    bf16* hp = (bf16*)base;
    bf16 h1 = __float2bfloat16(y1);
    bf16 h2 = __float2bfloat16(y2);
    hp[j]            = h1;
    hp[j + 64]       = h2;
    hp[128 + j]      = __float2bfloat16(y1 - __bfloat162float(h1));
    hp[128 + j + 64] = __float2bfloat16(y2 - __bfloat162float(h2));
}

// ---------------------------------------------------------------------------
// Flash attention: QK bf16 3-pass (R14-proven), PV fp16 2-pass.
// smem: Qh/Ql [128][272B]; per buf: Kh/Kl [64][272B], V16 [128][144B].
// Total = 69632 + 2*53248 = 176128 B.
// ---------------------------------------------------------------------------
#define AQH 0u
#define AQL 34816u
#define ABUF 69632u
#define BUFSZ 53248u
#define BKH 0u
#define BKL 17408u
#define BV  34816u

__global__ void __launch_bounds__(256) attn_hmma()
{
    extern __shared__ char smem[];
    const uint32_t sb = smem_u32(smem);
    const int t = threadIdx.x, lane = t & 31, wid = t >> 5;
    const int g = lane >> 2, qq = lane & 3;
    const int bx = blockIdx.x;
    const int qt = 31 - (bx >> 4);
    const int h  = bx & 15;
    const int r0 = qt * 128;
    const int jmax = 2 * qt + 1;

    const char* qbase = (const char*)g_heap + QOFF + ((size_t)(h * 4096 + r0)) * 512;
    const char* kbase = (const char*)g_heap + KOFF + ((size_t)h * 4096) * 512;

    {
        const char* src = qbase + (size_t)(t & 127) * 512 + (t >> 7) * 256;
        const uint32_t dst = sb + ((t >> 7) ? AQL : AQH) + (t & 127) * 272;
#pragma unroll
        for (int u = 0; u < 16; u++) CPA16(dst + u * 16, src + u * 16);
    }
    const int krow = t & 63, kseg = (t >> 6) & 1, kha = t >> 7;
    const int vrow = t & 127, vseg = t >> 7;
    const char* vsrc0 = (const char*)g_heap + VT16 +
                        ((size_t)h * 128 + vrow) * 8192 + vseg * 64;
    {
        const char* ksrc = kbase + (size_t)krow * 512 + kha * 256 + kseg * 128;
        const uint32_t kdst = sb + ABUF + (kha ? BKL : BKH) + krow * 272 + kseg * 128;
#pragma unroll
        for (int u = 0; u < 8; u++) CPA16(kdst + u * 16, ksrc + u * 16);
        const uint32_t vdst = sb + ABUF + BV + vrow * 144 + vseg * 64;
#pragma unroll
        for (int u = 0; u < 4; u++) CPA16(vdst + u * 16, vsrc0 + u * 16);
    }
    CPA_COMMIT();

    CPA_WAIT_ALL();
    __syncthreads();
    uint32_t qfh[8][4], qfl[8][4];
#pragma unroll
    for (int ks = 0; ks < 8; ks++) {
        const uint32_t qa = sb + AQH +
            (wid * 16 + (lane & 7) + ((lane >> 3) & 1) * 8) * 272 +
            ks * 32 + (lane >> 4) * 16;
        ldsm4(qfh[ks], qa);
        ldsm4(qfl[ks], qa + 34816);
    }

    float zacc[16][4];
#pragma unroll
    for (int n = 0; n < 16; n++)
#pragma unroll
        for (int r = 0; r < 4; r++) zacc[n][r] = 0.0f;
    float m0 = -3e38f, m1 = -3e38f, l0 = 0.0f, l1 = 0.0f;

    for (int j = 0; j <= jmax; j++) {
        const int b = j & 1;
        const uint32_t sbuf = sb + ABUF + b * BUFSZ;
        CPA_WAIT_ALL();
        __syncthreads();

        if (j < jmax) {
            const int col1 = (j + 1) * 64;
            const uint32_t ob = sb + ABUF + (b ^ 1) * BUFSZ;
            const char* ksrc = kbase + (size_t)(col1 + krow) * 512 + kha * 256 + kseg * 128;
            const uint32_t kdst = ob + (kha ? BKL : BKH) + krow * 272 + kseg * 128;
#pragma unroll
            for (int u = 0; u < 8; u++) CPA16(kdst + u * 16, ksrc + u * 16);
            const char* vsrc = vsrc0 + col1 * 2;
            const uint32_t vdst = ob + BV + vrow * 144 + vseg * 64;
#pragma unroll
            for (int u = 0; u < 4; u++) CPA16(vdst + u * 16, vsrc + u * 16);
            CPA_COMMIT();
        }

        float sacc[8][4];
#pragma unroll
        for (int n = 0; n < 8; n++)
#pragma unroll
            for (int r = 0; r < 4; r++) sacc[n][r] = 0.0f;

#pragma unroll
        for (int ks = 0; ks < 8; ks++) {
            uint32_t kh[4][4], kl[4][4];
#pragma unroll
            for (int n2 = 0; n2 < 4; n2++) {
                const uint32_t ka = sbuf + BKH +
                    (n2 * 16 + (lane & 7) + ((lane >> 4) & 1) * 8) * 272 +
                    ks * 32 + ((lane >> 3) & 1) * 16;
                ldsm4(kh[n2], ka);
                ldsm4(kl[n2], ka + 17408);
            }
#pragma unroll
            for (int n2 = 0; n2 < 4; n2++)
#pragma unroll
                for (int bb = 0; bb < 2; bb++)
                    mma16816(sacc[2 * n2 + bb], qfh[ks], &kh[n2][bb * 2]);
#pragma unroll
            for (int n2 = 0; n2 < 4; n2++)
#pragma unroll
                for (int bb = 0; bb < 2; bb++)
                    mma16816(sacc[2 * n2 + bb], qfl[ks], &kh[n2][bb * 2]);
#pragma unroll
            for (int n2 = 0; n2 < 4; n2++)
#pragma unroll
                for (int bb = 0; bb < 2; bb++)
                    mma16816(sacc[2 * n2 + bb], qfh[ks], &kl[n2][bb * 2]);
        }

        if (j >= 2 * qt) {
            const int rowlo = r0 + wid * 16 + g;
            const int colb  = j * 64 + qq * 2;
#pragma unroll
            for (int n = 0; n < 8; n++) {
                const int c0 = colb + n * 8, c1 = c0 + 1;
                if (c0 > rowlo)     sacc[n][0] = -1e30f;
                if (c1 > rowlo)     sacc[n][1] = -1e30f;
                if (c0 > rowlo + 8) sacc[n][2] = -1e30f;
                if (c1 > rowlo + 8) sacc[n][3] = -1e30f;
            }
        }

        float rm0 = -3e38f, rm1 = -3e38f;
#pragma unroll
        for (int n = 0; n < 8; n++) {
            rm0 = fmaxf(rm0, fmaxf(sacc[n][0], sacc[n][1]));
            rm1 = fmaxf(rm1, fmaxf(sacc[n][2], sacc[n][3]));
        }
        rm0 = fmaxf(rm0, __shfl_xor_sync(0xffffffffu, rm0, 1));
        rm0 = fmaxf(rm0, __shfl_xor_sync(0xffffffffu, rm0, 2));
        rm1 = fmaxf(rm1, __shfl_xor_sync(0xffffffffu, rm1, 1));
        rm1 = fmaxf(rm1, __shfl_xor_sync(0xffffffffu, rm1, 2));
        const float mn0 = fmaxf(m0, rm0), mn1 = fmaxf(m1, rm1);
        const float al0 = __expf(m0 - mn0), al1 = __expf(m1 - mn1);
        m0 = mn0; m1 = mn1;

        float rs0 = 0.0f, rs1 = 0.0f;
#pragma unroll
        for (int n = 0; n < 8; n++) {
            sacc[n][0] = __expf(sacc[n][0] - mn0);
            sacc[n][1] = __expf(sacc[n][1] - mn0);
            sacc[n][2] = __expf(sacc[n][2] - mn1);
            sacc[n][3] = __expf(sacc[n][3] - mn1);
            rs0 += sacc[n][0] + sacc[n][1];
            rs1 += sacc[n][2] + sacc[n][3];
        }
        rs0 += __shfl_xor_sync(0xffffffffu, rs0, 1);
        rs0 += __shfl_xor_sync(0xffffffffu, rs0, 2);
        rs1 += __shfl_xor_sync(0xffffffffu, rs1, 1);
        rs1 += __shfl_xor_sync(0xffffffffu, rs1, 2);
        l0 = l0 * al0 + rs0;
        l1 = l1 * al1 + rs1;

#pragma unroll
        for (int n = 0; n < 16; n++) {
            zacc[n][0] *= al0; zacc[n][1] *= al0;
            zacc[n][2] *= al1; zacc[n][3] *= al1;
        }

        // pack P as fp16 split A-fragments
        uint32_t pah[4][4], pal[4][4];
#pragma unroll
        for (int kt = 0; kt < 4; kt++) {
            pah[kt][0] = pack_split16(sacc[2*kt][0],   sacc[2*kt][1],   pal[kt][0]);
            pah[kt][1] = pack_split16(sacc[2*kt][2],   sacc[2*kt][3],   pal[kt][1]);
            pah[kt][2] = pack_split16(sacc[2*kt+1][0], sacc[2*kt+1][1], pal[kt][2]);
            pah[kt][3] = pack_split16(sacc[2*kt+1][2], sacc[2*kt+1][3], pal[kt][3]);
        }

        // Z += P @ V : fp16 2-pass, pass-major per kt
#pragma unroll
        for (int kt = 0; kt < 4; kt++) {
            uint32_t vv[8][4];
#pragma unroll
            for (int n2 = 0; n2 < 8; n2++) {
                const uint32_t va = sbuf + BV +
                    (n2 * 16 + (lane & 7) + ((lane >> 4) & 1) * 8) * 144 +
                    kt * 32 + ((lane >> 3) & 1) * 16;
                ldsm4(vv[n2], va);
            }
#pragma unroll
            for (int n2 = 0; n2 < 8; n2++)
#pragma unroll
                for (int bb = 0; bb < 2; bb++)
                    mma_f16(zacc[2 * n2 + bb], pah[kt], &vv[n2][bb * 2]);
#pragma unroll
            for (int n2 = 0; n2 < 8; n2++)
#pragma unroll
                for (int bb = 0; bb < 2; bb++)
                    mma_f16(zacc[2 * n2 + bb], pal[kt], &vv[n2][bb * 2]);
        }
        __syncthreads();
    }

    // normalize + split z -> zh/zl fp16
    const float i0 = 1.0f / l0, i1 = 1.0f / l1;
    uint32_t* zh = (uint32_t*)(g_heap + ZH16);
    uint32_t* zl = (uint32_t*)(g_heap + ZL16);
    const int rowlo = r0 + wid * 16 + g;
#pragma unroll
    for (int n = 0; n < 16; n++) {
        const int col = h * 128 + n * 8 + qq * 2;
        uint32_t lo_pk, hi_pk;
        hi_pk = pack_split16(zacc[n][0] * i0, zacc[n][1] * i0, lo_pk);
        zh[((size_t)rowlo * 2048 + col) >> 1] = hi_pk;
        zl[((size_t)rowlo * 2048 + col) >> 1] = lo_pk;
        hi_pk = pack_split16(zacc[n][2] * i1, zacc[n][3] * i1, lo_pk);
        zh[((size_t)(rowlo + 8) * 2048 + col) >> 1] = hi_pk;
        zl[((size_t)(rowlo + 8) * 2048 + col) >> 1] = lo_pk;
    }
}

// ---------------------------------------------------------------------------
extern "C" void kernel_launch(void* const* d_in, const int* in_sizes, int n_in,
                              void* d_out, int out_size)
{
    const float* x     = (const float*)d_in[0];
    const float* q     = (const float*)d_in[1];
    const float* k     = (const float*)d_in[2];
    const float* v     = (const float*)d_in[3];
    const float* o     = (const float*)d_in[4];
    const float* theta = (const float*)d_in[5];
    float* out = (float*)d_out;

    cudaFuncSetAttribute(attn_hmma,
                         cudaFuncAttributeMaxDynamicSharedMemorySize, 176128);

    cvtx16s<<<8192, 256>>>(x);
    splitwT<<<dim3(64, 4, 16), dim3(32, 8)>>>(q);
    proj_v9<<<dim3(32, 16), 512>>>(x, QOFF);
    splitwT<<<dim3(64, 4, 16), dim3(32, 8)>>>(k);
    proj_v9<<<dim3(32, 16), 512>>>(x, KOFF);
    vproj16<<<dim3(32, 16), 512>>>(v);
    rope_pack<<<dim3(1024, 16, 2), 256>>>(theta);
    attn_hmma<<<512, 256, 176128>>>();
    outproj16<<<dim3(32, 16), 512>>>(out, o);
}

// round 17
// speedup vs baseline: 1.1973x; 1.0813x over previous
#include <cuda_runtime.h>
#include <cuda_bf16.h>
#include <cuda_fp16.h>
#include <math.h>
#include <stdint.h>

#define SEQ 4096
#define DM  2048
#define NH  16
#define DQK 128

typedef __nv_bfloat16 bf16;

// ---------------- single 128 MiB heap, phase-overlaid (R16 layout) ----------
// [0,32M)    Q fp32 proj -> rope-packed bf16 hi|lo rows
// [32,64M)   K same
// [64,80M)   x16 hi -> (vproj) -> z16 single fp16 (attn out)
// [80,96M)   x16 lo -> dead after vproj
// [96,112M)  vT fp16 [h][v][s]
// [112,128M) W bf16 split scratch
__device__ __align__(1024) unsigned char g_heap[134217728];
#define QOFF 0u
#define KOFF 33554432u
#define XH16 67108864u
#define XL16 83886080u
#define ZS16 67108864u
#define VT16 100663296u
#define WH   117440512u
#define WL   125829120u

// ---------------- helpers ---------------------------------------------------
__device__ __forceinline__ void mma16816(float* c, const uint32_t* a, const uint32_t* b) {
    asm volatile(
        "mma.sync.aligned.m16n8k16.row.col.f32.bf16.bf16.f32 "
        "{%0,%1,%2,%3}, {%4,%5,%6,%7}, {%8,%9}, {%0,%1,%2,%3};"
        : "+f"(c[0]), "+f"(c[1]), "+f"(c[2]), "+f"(c[3])
        : "r"(a[0]), "r"(a[1]), "r"(a[2]), "r"(a[3]), "r"(b[0]), "r"(b[1]));
}
__device__ __forceinline__ void mma_f16(float* c, const uint32_t* a, const uint32_t* b) {
    asm volatile(
        "mma.sync.aligned.m16n8k16.row.col.f32.f16.f16.f32 "
        "{%0,%1,%2,%3}, {%4,%5,%6,%7}, {%8,%9}, {%0,%1,%2,%3};"
        : "+f"(c[0]), "+f"(c[1]), "+f"(c[2]), "+f"(c[3])
        : "r"(a[0]), "r"(a[1]), "r"(a[2]), "r"(a[3]), "r"(b[0]), "r"(b[1]));
}
__device__ __forceinline__ void ldsm4(uint32_t* r, uint32_t a) {
    asm volatile("ldmatrix.sync.aligned.m8n8.x4.shared.b16 {%0,%1,%2,%3}, [%4];"
                 : "=r"(r[0]), "=r"(r[1]), "=r"(r[2]), "=r"(r[3]) : "r"(a));
}
__device__ __forceinline__ uint32_t smem_u32(const void* p) {
    uint32_t a;
    asm("{ .reg .u64 t; cvta.to.shared.u64 t, %1; cvt.u32.u64 %0, t; }"
        : "=r"(a) : "l"(p));
    return a;
}
#define CPA16(dst, src) \
    asm volatile("cp.async.cg.shared.global [%0], [%1], 16;" :: "r"(dst), "l"(src))
#define CPA_COMMIT() asm volatile("cp.async.commit_group;" ::: "memory")
#define CPA_WAIT_ALL() asm volatile("cp.async.wait_all;" ::: "memory")
#define CPA_WAIT1() asm volatile("cp.async.wait_group 1;" ::: "memory")

__device__ __forceinline__ uint32_t pack_split(float a, float b, uint32_t& lopk) {
    bf16 ha = __float2bfloat16(a), hb = __float2bfloat16(b);
    bf16 la = __float2bfloat16(a - __bfloat162float(ha));
    bf16 lb = __float2bfloat16(b - __bfloat162float(hb));
    lopk = (uint32_t)__bfloat16_as_ushort(la) |
           ((uint32_t)__bfloat16_as_ushort(lb) << 16);
    return (uint32_t)__bfloat16_as_ushort(ha) |
           ((uint32_t)__bfloat16_as_ushort(hb) << 16);
}
__device__ __forceinline__ uint32_t pack_split16(float a, float b, uint32_t& lopk) {
    __half ha = __float2half_rn(a), hb = __float2half_rn(b);
    __half la = __float2half_rn(a - __half2float(ha));
    __half lb = __float2half_rn(b - __half2float(hb));
    lopk = (uint32_t)__half_as_ushort(la) | ((uint32_t)__half_as_ushort(lb) << 16);
    return (uint32_t)__half_as_ushort(ha) | ((uint32_t)__half_as_ushort(hb) << 16);
}
__device__ __forceinline__ uint32_t pack_h2(float a, float b) {
    __half2 w = __floats2half2_rn(a, b);
    return *(uint32_t*)&w;
}

// ---------------------------------------------------------------------------
// GEMM v9 (R14-proven, bf16 3-pass) for Q/K projections.
// ---------------------------------------------------------------------------
__device__ __forceinline__ void gemm_v9(
    const float* __restrict__ A, int lda,
    const bf16* __restrict__ Bh, const bf16* __restrict__ Bl, int ldb,
    float* __restrict__ C, int ldc, float scale)
{
    __shared__ __align__(16) unsigned char sm[122880];
    const uint32_t sb = smem_u32(sm);

    const int t = threadIdx.x, lane = t & 31, wid = t >> 5;
    const int wm = (wid >> 3) * 64, wn = (wid & 7) * 16;

    const int arow = t >> 2, aseg = t & 3;
    const float* pA = A + (size_t)arow * lda + aseg * 8;
    const uint32_t asoff = arow * 80u + aseg * 16u;

    const int bt = t >> 8, brow = (t >> 1) & 127, bseg = t & 1;
    const char* pB = (const char*)((bt ? Bl : Bh) + (size_t)brow * ldb) + bseg * 32;
    const uint32_t bsoff = 20480u + bt * 10240u + brow * 80u + bseg * 32u;

    float acc[4][2][4];
#pragma unroll
    for (int i = 0; i < 4; i++)
#pragma unroll
        for (int j = 0; j < 2; j++)
#pragma unroll
            for (int r = 0; r < 4; r++) acc[i][j][r] = 0.0f;

    float a_f[8];
#define PREF_A(kc) do { \
        const float* ap_ = pA + (size_t)(kc) * 32; \
        float4 v0_ = *(const float4*)ap_; \
        float4 v1_ = *(const float4*)(ap_ + 4); \
        a_f[0] = v0_.x; a_f[1] = v0_.y; a_f[2] = v0_.z; a_f[3] = v0_.w; \
        a_f[4] = v1_.x; a_f[5] = v1_.y; a_f[6] = v1_.z; a_f[7] = v1_.w; \
    } while (0)
#define PACK_A(st) do { \
        uint32_t hi_[4], lo_[4]; \
        hi_[0] = pack_split(a_f[0], a_f[1], lo_[0]); \
        hi_[1] = pack_split(a_f[2], a_f[3], lo_[1]); \
        hi_[2] = pack_split(a_f[4], a_f[5], lo_[2]); \
        hi_[3] = pack_split(a_f[6], a_f[7], lo_[3]); \
        *(uint4*)(sm + (st) + asoff)         = make_uint4(hi_[0], hi_[1], hi_[2], hi_[3]); \
        *(uint4*)(sm + (st) + 10240 + asoff) = make_uint4(lo_[0], lo_[1], lo_[2], lo_[3]); \
    } while (0)
#define ISSUE_B(kc, st) do { \
        const char* src_ = pB + (size_t)(kc) * 64; \
        CPA16(sb + (st) + bsoff, src_); \
        CPA16(sb + (st) + bsoff + 16, src_ + 16); \
        CPA_COMMIT(); \
    } while (0)

    PREF_A(0); PACK_A(0u);      ISSUE_B(0, 0u);
    PREF_A(1); PACK_A(40960u);  ISSUE_B(1, 40960u);
    PREF_A(2);

    uint32_t cur = 0u, fill = 81920u;
    for (int kc = 0; kc < 64; kc++) {
        if (kc < 63) CPA_WAIT1();
        else         CPA_WAIT_ALL();
        __syncthreads();

        if (kc + 2 < 64) {
            PACK_A(fill);
            ISSUE_B(kc + 2, fill);
            if (kc + 3 < 64) PREF_A(kc + 3);
        }

#pragma unroll
        for (int ks = 0; ks < 2; ks++) {
            uint32_t ah[4][4], al[4][4], bh4[4], bl4[4];
            const uint32_t abase = sb + cur +
                (wm + (lane & 7) + ((lane >> 3) & 1) * 8) * 80 + ks * 32 + (lane >> 4) * 16;
#pragma unroll
            for (int i = 0; i < 4; i++) {
                ldsm4(ah[i], abase + i * 1280);
                ldsm4(al[i], abase + 10240 + i * 1280);
            }
            const uint32_t bbase = sb + cur + 20480 +
                (wn + (lane & 7) + ((lane >> 4) & 1) * 8) * 80 + ks * 32 + ((lane >> 3) & 1) * 16;
            ldsm4(bh4, bbase);
            ldsm4(bl4, bbase + 10240);
#pragma unroll
            for (int i = 0; i < 4; i++)
#pragma unroll
                for (int j = 0; j < 2; j++)
                    mma16816(acc[i][j], ah[i], &bh4[j * 2]);
#pragma unroll
            for (int i = 0; i < 4; i++)
#pragma unroll
                for (int j = 0; j < 2; j++)
                    mma16816(acc[i][j], al[i], &bh4[j * 2]);
#pragma unroll
            for (int i = 0; i < 4; i++)
#pragma unroll
                for (int j = 0; j < 2; j++)
                    mma16816(acc[i][j], ah[i], &bl4[j * 2]);
        }

        cur  = (cur  == 81920u) ? 0u : cur  + 40960u;
        fill = (fill == 81920u) ? 0u : fill + 40960u;
    }
#undef PREF_A
#undef PACK_A
#undef ISSUE_B

    const int g = lane >> 2, qq = lane & 3;
#pragma unroll
    for (int i = 0; i < 4; i++)
#pragma unroll
        for (int j = 0; j < 2; j++) {
            const int row = wm + i * 16 + g;
            const int col = wn + j * 8 + qq * 2;
            float2 lo = make_float2(acc[i][j][0] * scale, acc[i][j][1] * scale);
            float2 hi = make_float2(acc[i][j][2] * scale, acc[i][j][3] * scale);
            *(float2*)(C + (size_t)row * ldc + col)       = lo;
            *(float2*)(C + (size_t)(row + 8) * ldc + col) = hi;
        }
}

__global__ void __launch_bounds__(512) proj_v9(const float* __restrict__ x,
                                              unsigned dstoff)
{
    const int h = blockIdx.y;
    const bf16* bh = (const bf16*)(g_heap + WH) + (size_t)h * 262144;
    const bf16* bl = (const bf16*)(g_heap + WL) + (size_t)h * 262144;
    float* C = (float*)(g_heap + dstoff) +
               (size_t)h * SEQ * DQK + (size_t)blockIdx.x * 128 * DQK;
    gemm_v9(x + (size_t)blockIdx.x * 128 * DM, DM, bh, bl, DM, C, DQK, 1.0f);
}

// ---------------------------------------------------------------------------
// GEMM 2-pass fp16 (R16-proven): vproj (mode 1 = transposed fp16 scatter).
// ---------------------------------------------------------------------------
__device__ __forceinline__ void gemm_2p(
    const __half* __restrict__ Ah, const __half* __restrict__ Al, int lda,
    const float* __restrict__ Bf, int ldbn,
    __half* __restrict__ vtb, int s0)
{
    __shared__ __align__(16) unsigned char sm[61440];
    const uint32_t sb = smem_u32(sm);

    const int t = threadIdx.x, lane = t & 31, wid = t >> 5;
    const int wm = (wid >> 3) * 64, wn = (wid & 7) * 16;

    const int arow = t >> 2, aseg = t & 3;
    const char* pAh = (const char*)(Ah + (size_t)arow * lda) + aseg * 16;
    const char* pAl = (const char*)(Al + (size_t)arow * lda) + aseg * 16;
    const uint32_t asoff = arow * 80u + aseg * 16u;

    const int kp = t >> 5, nb = (t & 31) * 4;
    const float* pB0 = Bf + (size_t)(2 * kp) * ldbn + nb;
    const float* pB1 = pB0 + ldbn;

    float acc[4][2][4];
#pragma unroll
    for (int i = 0; i < 4; i++)
#pragma unroll
        for (int j = 0; j < 2; j++)
#pragma unroll
            for (int r = 0; r < 4; r++) acc[i][j][r] = 0.0f;

    float b_f[8];
#define PREF_B(kc) do { \
        const float* b0_ = pB0 + (size_t)(kc) * 32 * ldbn; \
        const float* b1_ = pB1 + (size_t)(kc) * 32 * ldbn; \
        float4 v0_ = *(const float4*)b0_; \
        float4 v1_ = *(const float4*)b1_; \
        b_f[0] = v0_.x; b_f[1] = v0_.y; b_f[2] = v0_.z; b_f[3] = v0_.w; \
        b_f[4] = v1_.x; b_f[5] = v1_.y; b_f[6] = v1_.z; b_f[7] = v1_.w; \
    } while (0)
#define ISSUE_A2(kc, st) do { \
        CPA16(sb + (st) + asoff,         pAh + (size_t)(kc) * 64); \
        CPA16(sb + (st) + 10240 + asoff, pAl + (size_t)(kc) * 64); \
        CPA_COMMIT(); \
    } while (0)

    PREF_B(0);
    ISSUE_A2(0, 0u);

    for (int kc = 0; kc < 64; kc++) {
        const uint32_t st = (kc & 1) * 30720u;
        __syncthreads();
        {
            uint32_t* bs = (uint32_t*)(sm + st + 20480);
#pragma unroll
            for (int i = 0; i < 4; i++)
                bs[(nb + i) * 20 + kp] = pack_h2(b_f[i], b_f[4 + i]);
        }
        if (kc < 63) {
            ISSUE_A2(kc + 1, st ^ 30720u);
            PREF_B(kc + 1);
            CPA_WAIT1();
        } else {
            CPA_WAIT_ALL();
        }
        __syncthreads();

#pragma unroll
        for (int ks = 0; ks < 2; ks++) {
            uint32_t ah[4][4], al[4][4], b4[4];
            const uint32_t abase = sb + st +
                (wm + (lane & 7) + ((lane >> 3) & 1) * 8) * 80 + ks * 32 + (lane >> 4) * 16;
#pragma unroll
            for (int i = 0; i < 4; i++) {
                ldsm4(ah[i], abase + i * 1280);
                ldsm4(al[i], abase + 10240 + i * 1280);
            }
            const uint32_t bbase = sb + st + 20480 +
                (wn + (lane & 7) + ((lane >> 4) & 1) * 8) * 80 + ks * 32 + ((lane >> 3) & 1) * 16;
            ldsm4(b4, bbase);
#pragma unroll
            for (int i = 0; i < 4; i++)
#pragma unroll
                for (int j = 0; j < 2; j++)
                    mma_f16(acc[i][j], ah[i], &b4[j * 2]);
#pragma unroll
            for (int i = 0; i < 4; i++)
#pragma unroll
                for (int j = 0; j < 2; j++)
                    mma_f16(acc[i][j], al[i], &b4[j * 2]);
        }
    }
#undef PREF_B
#undef ISSUE_A2

    const int g = lane >> 2, qq = lane & 3;
#pragma unroll
    for (int i = 0; i < 4; i++)
#pragma unroll
        for (int j = 0; j < 2; j++) {
            const int row = wm + i * 16 + g;
            const int col = wn + j * 8 + qq * 2;
            vtb[(size_t)col * 4096 + s0 + row]           = __float2half_rn(acc[i][j][0]);
            vtb[(size_t)(col + 1) * 4096 + s0 + row]     = __float2half_rn(acc[i][j][1]);
            vtb[(size_t)col * 4096 + s0 + row + 8]       = __float2half_rn(acc[i][j][2]);
            vtb[(size_t)(col + 1) * 4096 + s0 + row + 8] = __float2half_rn(acc[i][j][3]);
        }
}

__global__ void __launch_bounds__(512) vproj16(const float* __restrict__ v)
{
    const int h = blockIdx.y;
    gemm_2p((const __half*)(g_heap + XH16) + (size_t)blockIdx.x * 128 * DM,
            (const __half*)(g_heap + XL16) + (size_t)blockIdx.x * 128 * DM, DM,
            v + (size_t)h * DM * DQK, DQK,
            (__half*)(g_heap + VT16) + (size_t)h * 128 * 4096, blockIdx.x * 128);
}

// ---------------------------------------------------------------------------
// GEMM 1-pass fp16: A = single fp16 (cp.async), B = fp32 cvt in-loader.
// Stage (20480 B): A16 +0 (10240), B16 +10240. Same ldsm/mma mapping.
// ---------------------------------------------------------------------------
__global__ void __launch_bounds__(512) outproj1p(float* __restrict__ out,
                                                const float* __restrict__ o)
{
    __shared__ __align__(16) unsigned char sm[40960];
    const uint32_t sb = smem_u32(sm);

    const __half* A = (const __half*)(g_heap + ZS16) + (size_t)blockIdx.x * 128 * 2048;
    const float* Bf = o + blockIdx.y * 128;
    float* Cf = out + (size_t)blockIdx.x * 128 * DM + blockIdx.y * 128;

    const int t = threadIdx.x, lane = t & 31, wid = t >> 5;
    const int wm = (wid >> 3) * 64, wn = (wid & 7) * 16;

    const int arow = t >> 2, aseg = t & 3;
    const char* pA = (const char*)(A + (size_t)arow * 2048) + aseg * 16;
    const uint32_t asoff = arow * 80u + aseg * 16u;

    const int kp = t >> 5, nb = (t & 31) * 4;
    const float* pB0 = Bf + (size_t)(2 * kp) * 2048 + nb;
    const float* pB1 = pB0 + 2048;

    float acc[4][2][4];
#pragma unroll
    for (int i = 0; i < 4; i++)
#pragma unroll
        for (int j = 0; j < 2; j++)
#pragma unroll
            for (int r = 0; r < 4; r++) acc[i][j][r] = 0.0f;

    float b_f[8];
#define PREF_B1(kc) do { \
        const float* b0_ = pB0 + (size_t)(kc) * 32 * 2048; \
        const float* b1_ = pB1 + (size_t)(kc) * 32 * 2048; \
        float4 v0_ = *(const float4*)b0_; \
        float4 v1_ = *(const float4*)b1_; \
        b_f[0] = v0_.x; b_f[1] = v0_.y; b_f[2] = v0_.z; b_f[3] = v0_.w; \
        b_f[4] = v1_.x; b_f[5] = v1_.y; b_f[6] = v1_.z; b_f[7] = v1_.w; \
    } while (0)

    PREF_B1(0);
    CPA16(sb + asoff, pA);
    CPA_COMMIT();

    for (int kc = 0; kc < 64; kc++) {
        const uint32_t st = (kc & 1) * 20480u;
        __syncthreads();
        {
            uint32_t* bs = (uint32_t*)(sm + st + 10240);
#pragma unroll
            for (int i = 0; i < 4; i++)
                bs[(nb + i) * 20 + kp] = pack_h2(b_f[i], b_f[4 + i]);
        }
        if (kc < 63) {
            CPA16(sb + (st ^ 20480u) + asoff, pA + (size_t)(kc + 1) * 64);
            CPA_COMMIT();
            PREF_B1(kc + 1);
            CPA_WAIT1();
        } else {
            CPA_WAIT_ALL();
        }
        __syncthreads();

#pragma unroll
        for (int ks = 0; ks < 2; ks++) {
            uint32_t a4[4][4], b4[4];
            const uint32_t abase = sb + st +
                (wm + (lane & 7) + ((lane >> 3) & 1) * 8) * 80 + ks * 32 + (lane >> 4) * 16;
#pragma unroll
            for (int i = 0; i < 4; i++) ldsm4(a4[i], abase + i * 1280);
            const uint32_t bbase = sb + st + 10240 +
                (wn + (lane & 7) + ((lane >> 4) & 1) * 8) * 80 + ks * 32 + ((lane >> 3) & 1) * 16;
            ldsm4(b4, bbase);
#pragma unroll
            for (int i = 0; i < 4; i++)
#pragma unroll
                for (int j = 0; j < 2; j++)
                    mma_f16(acc[i][j], a4[i], &b4[j * 2]);
        }
    }
#undef PREF_B1

    const int g = lane >> 2, qq = lane & 3;
#pragma unroll
    for (int i = 0; i < 4; i++)
#pragma unroll
        for (int j = 0; j < 2; j++) {
            const int row = wm + i * 16 + g;
            const int col = wn + j * 8 + qq * 2;
            float2 lo = make_float2(acc[i][j][0] * 4.8828125e-4f, acc[i][j][1] * 4.8828125e-4f);
            float2 hi = make_float2(acc[i][j][2] * 4.8828125e-4f, acc[i][j][3] * 4.8828125e-4f);
            *(float2*)(Cf + (size_t)row * DM + col)       = lo;
            *(float2*)(Cf + (size_t)(row + 8) * DM + col) = hi;
        }
}

// ---------------------------------------------------------------------------
// prep kernels (R16-verbatim)
// ---------------------------------------------------------------------------
__global__ void __launch_bounds__(256) splitwT(const float* __restrict__ w)
{
    __shared__ float tile[32][33];
    const int h = blockIdx.z;
    const float* src = w + (size_t)h * 262144;
    bf16* oh = (bf16*)(g_heap + WH) + (size_t)h * 262144;
    bf16* ol = (bf16*)(g_heap + WL) + (size_t)h * 262144;
    const int tx = threadIdx.x, ty = threadIdx.y;
    const int k0 = blockIdx.x * 32, n0 = blockIdx.y * 32;
#pragma unroll
    for (int i = 0; i < 4; i++)
        tile[ty + 8 * i][tx] = src[(size_t)(k0 + ty + 8 * i) * 128 + n0 + tx];
    __syncthreads();
#pragma unroll
    for (int i = 0; i < 4; i++) {
        float v = tile[tx][ty + 8 * i];
        bf16 hh = __float2bfloat16(v);
        oh[(size_t)(n0 + ty + 8 * i) * 2048 + k0 + tx] = hh;
        ol[(size_t)(n0 + ty + 8 * i) * 2048 + k0 + tx] =
            __float2bfloat16(v - __bfloat162float(hh));
    }
}

__global__ void __launch_bounds__(256) cvtx16s(const float* __restrict__ x)
{
    const size_t i = ((size_t)blockIdx.x * 256 + threadIdx.x) * 4;
    float4 vv = *(const float4*)(x + i);
    uint32_t hi0, hi1, lo0, lo1;
    hi0 = pack_split16(vv.x, vv.y, lo0);
    hi1 = pack_split16(vv.z, vv.w, lo1);
    *(uint2*)((__half*)(g_heap + XH16) + i) = make_uint2(hi0, hi1);
    *(uint2*)((__half*)(g_heap + XL16) + i) = make_uint2(lo0, lo1);
}

__global__ void __launch_bounds__(256) rope_pack(const float* __restrict__ theta)
{
    const float tf = theta[0];
    const int s = blockIdx.x * 4 + (threadIdx.x >> 6);
    const int j = threadIdx.x & 63;
    const int h = blockIdx.y;
    char* base = (char*)g_heap + (blockIdx.z ? KOFF : QOFF) +
                 ((size_t)(h * 4096 + s)) * 512;
    float* rowp = (float*)base;

    const float x1 = rowp[j];
    const float x2 = rowp[j + 64];
    const float rate = tf * (-(float)j * 0.015625f);
    const float rot  = __fmul_rn((float)s, rate);
    float sv, cv;
    sincosf(rot, &sv, &cv);
    const float y1 = (cv * x1 - sv * x2) / 3.36358566101485845f;
    const float y2 = (sv * x1 + cv * x2) / 3.36358566101485845f;

    __syncthreads();

    bf16* hp = (bf16*)base;
    bf16 h1 = __float2bfloat16(y1);
    bf16 h2 = __float2bfloat16(y2);
    hp[j]            = h1;
    hp[j + 64]       = h2;
    hp[128 + j]      = __float2bfloat16(y1 - __bfloat162float(h1));
    hp[128 + j + 64] = __float2bfloat16(y2 - __bfloat162float(h2));
}

// ---------------------------------------------------------------------------
// Flash attention: QK bf16 3-pass (proven), PV fp16 1-PASS (P single fp16).
// smem: Qh/Ql [128][272B]; per buf: Kh/Kl [64][272B], V16 [128][144B].
// ---------------------------------------------------------------------------
#define AQH 0u
#define AQL 34816u
#define ABUF 69632u
#define BUFSZ 53248u
#define BKH 0u
#define BKL 17408u
#define BV  34816u

__global__ void __launch_bounds__(256) attn_hmma()
{
    extern __shared__ char smem[];
    const uint32_t sb = smem_u32(smem);
    const int t = threadIdx.x, lane = t & 31, wid = t >> 5;
    const int g = lane >> 2, qq = lane & 3;
    const int bx = blockIdx.x;
    const int qt = 31 - (bx >> 4);
    const int h  = bx & 15;
    const int r0 = qt * 128;
    const int jmax = 2 * qt + 1;

    const char* qbase = (const char*)g_heap + QOFF + ((size_t)(h * 4096 + r0)) * 512;
    const char* kbase = (const char*)g_heap + KOFF + ((size_t)h * 4096) * 512;

    {
        const char* src = qbase + (size_t)(t & 127) * 512 + (t >> 7) * 256;
        const uint32_t dst = sb + ((t >> 7) ? AQL : AQH) + (t & 127) * 272;
#pragma unroll
        for (int u = 0; u < 16; u++) CPA16(dst + u * 16, src + u * 16);
    }
    const int krow = t & 63, kseg = (t >> 6) & 1, kha = t >> 7;
    const int vrow = t & 127, vseg = t >> 7;
    const char* vsrc0 = (const char*)g_heap + VT16 +
                        ((size_t)h * 128 + vrow) * 8192 + vseg * 64;
    {
        const char* ksrc = kbase + (size_t)krow * 512 + kha * 256 + kseg * 128;
        const uint32_t kdst = sb + ABUF + (kha ? BKL : BKH) + krow * 272 + kseg * 128;
#pragma unroll
        for (int u = 0; u < 8; u++) CPA16(kdst + u * 16, ksrc + u * 16);
        const uint32_t vdst = sb + ABUF + BV + vrow * 144 + vseg * 64;
#pragma unroll
        for (int u = 0; u < 4; u++) CPA16(vdst + u * 16, vsrc0 + u * 16);
    }
    CPA_COMMIT();

    CPA_WAIT_ALL();
    __syncthreads();
    uint32_t qfh[8][4], qfl[8][4];
#pragma unroll
    for (int ks = 0; ks < 8; ks++) {
        const uint32_t qa = sb + AQH +
            (wid * 16 + (lane & 7) + ((lane >> 3) & 1) * 8) * 272 +
            ks * 32 + (lane >> 4) * 16;
        ldsm4(qfh[ks], qa);
        ldsm4(qfl[ks], qa + 34816);
    }

    float zacc[16][4];
#pragma unroll
    for (int n = 0; n < 16; n++)
#pragma unroll
        for (int r = 0; r < 4; r++) zacc[n][r] = 0.0f;
    float m0 = -3e38f, m1 = -3e38f, l0 = 0.0f, l1 = 0.0f;

    for (int j = 0; j <= jmax; j++) {
        const int b = j & 1;
        const uint32_t sbuf = sb + ABUF + b * BUFSZ;
        CPA_WAIT_ALL();
        __syncthreads();

        if (j < jmax) {
            const int col1 = (j + 1) * 64;
            const uint32_t ob = sb + ABUF + (b ^ 1) * BUFSZ;
            const char* ksrc = kbase + (size_t)(col1 + krow) * 512 + kha * 256 + kseg * 128;
            const uint32_t kdst = ob + (kha ? BKL : BKH) + krow * 272 + kseg * 128;
#pragma unroll
            for (int u = 0; u < 8; u++) CPA16(kdst + u * 16, ksrc + u * 16);
            const char* vsrc = vsrc0 + col1 * 2;
            const uint32_t vdst = ob + BV + vrow * 144 + vseg * 64;
#pragma unroll
            for (int u = 0; u < 4; u++) CPA16(vdst + u * 16, vsrc + u * 16);
            CPA_COMMIT();
        }

        float sacc[8][4];
#pragma unroll
        for (int n = 0; n < 8; n++)
#pragma unroll
            for (int r = 0; r < 4; r++) sacc[n][r] = 0.0f;

#pragma unroll
        for (int ks = 0; ks < 8; ks++) {
            uint32_t kh[4][4], kl[4][4];
#pragma unroll
            for (int n2 = 0; n2 < 4; n2++) {
                const uint32_t ka = sbuf + BKH +
                    (n2 * 16 + (lane & 7) + ((lane >> 4) & 1) * 8) * 272 +
                    ks * 32 + ((lane >> 3) & 1) * 16;
                ldsm4(kh[n2], ka);
                ldsm4(kl[n2], ka + 17408);
            }
#pragma unroll
            for (int n2 = 0; n2 < 4; n2++)
#pragma unroll
                for (int bb = 0; bb < 2; bb++)
                    mma16816(sacc[2 * n2 + bb], qfh[ks], &kh[n2][bb * 2]);
#pragma unroll
            for (int n2 = 0; n2 < 4; n2++)
#pragma unroll
                for (int bb = 0; bb < 2; bb++)
                    mma16816(sacc[2 * n2 + bb], qfl[ks], &kh[n2][bb * 2]);
#pragma unroll
            for (int n2 = 0; n2 < 4; n2++)
#pragma unroll
                for (int bb = 0; bb < 2; bb++)
                    mma16816(sacc[2 * n2 + bb], qfh[ks], &kl[n2][bb * 2]);
        }

        if (j >= 2 * qt) {
            const int rowlo = r0 + wid * 16 + g;
            const int colb  = j * 64 + qq * 2;
#pragma unroll
            for (int n = 0; n < 8; n++) {
                const int c0 = colb + n * 8, c1 = c0 + 1;
                if (c0 > rowlo)     sacc[n][0] = -1e30f;
                if (c1 > rowlo)     sacc[n][1] = -1e30f;
                if (c0 > rowlo + 8) sacc[n][2] = -1e30f;
                if (c1 > rowlo + 8) sacc[n][3] = -1e30f;
            }
        }

        float rm0 = -3e38f, rm1 = -3e38f;
#pragma unroll
        for (int n = 0; n < 8; n++) {
            rm0 = fmaxf(rm0, fmaxf(sacc[n][0], sacc[n][1]));
            rm1 = fmaxf(rm1, fmaxf(sacc[n][2], sacc[n][3]));
        }
        rm0 = fmaxf(rm0, __shfl_xor_sync(0xffffffffu, rm0, 1));
        rm0 = fmaxf(rm0, __shfl_xor_sync(0xffffffffu, rm0, 2));
        rm1 = fmaxf(rm1, __shfl_xor_sync(0xffffffffu, rm1, 1));
        rm1 = fmaxf(rm1, __shfl_xor_sync(0xffffffffu, rm1, 2));
        const float mn0 = fmaxf(m0, rm0), mn1 = fmaxf(m1, rm1);
        const float al0 = __expf(m0 - mn0), al1 = __expf(m1 - mn1);
        m0 = mn0; m1 = mn1;

        float rs0 = 0.0f, rs1 = 0.0f;
#pragma unroll
        for (int n = 0; n < 8; n++) {
            sacc[n][0] = __expf(sacc[n][0] - mn0);
            sacc[n][1] = __expf(sacc[n][1] - mn0);
            sacc[n][2] = __expf(sacc[n][2] - mn1);
            sacc[n][3] = __expf(sacc[n][3] - mn1);
            rs0 += sacc[n][0] + sacc[n][1];
            rs1 += sacc[n][2] + sacc[n][3];
        }
        rs0 += __shfl_xor_sync(0xffffffffu, rs0, 1);
        rs0 += __shfl_xor_sync(0xffffffffu, rs0, 2);
        rs1 += __shfl_xor_sync(0xffffffffu, rs1, 1);
        rs1 += __shfl_xor_sync(0xffffffffu, rs1, 2);
        l0 = l0 * al0 + rs0;
        l1 = l1 * al1 + rs1;

#pragma unroll
        for (int n = 0; n < 16; n++) {
            zacc[n][0] *= al0; zacc[n][1] *= al0;
            zacc[n][2] *= al1; zacc[n][3] *= al1;
        }

        // pack P as SINGLE fp16 A-fragments
        uint32_t pah[4][4];
#pragma unroll
        for (int kt = 0; kt < 4; kt++) {
            pah[kt][0] = pack_h2(sacc[2*kt][0],   sacc[2*kt][1]);
            pah[kt][1] = pack_h2(sacc[2*kt][2],   sacc[2*kt][3]);
            pah[kt][2] = pack_h2(sacc[2*kt+1][0], sacc[2*kt+1][1]);
            pah[kt][3] = pack_h2(sacc[2*kt+1][2], sacc[2*kt+1][3]);
        }

        // Z += P @ V : fp16 1-pass
#pragma unroll
        for (int kt = 0; kt < 4; kt++) {
            uint32_t vv[8][4];
#pragma unroll
            for (int n2 = 0; n2 < 8; n2++) {
                const uint32_t va = sbuf + BV +
                    (n2 * 16 + (lane & 7) + ((lane >> 4) & 1) * 8) * 144 +
                    kt * 32 + ((lane >> 3) & 1) * 16;
                ldsm4(vv[n2], va);
            }
#pragma unroll
            for (int n2 = 0; n2 < 8; n2++)
#pragma unroll
                for (int bb = 0; bb < 2; bb++)
                    mma_f16(zacc[2 * n2 + bb], pah[kt], &vv[n2][bb * 2]);
        }
        __syncthreads();
    }

    // normalize + write z SINGLE fp16
    const float i0 = 1.0f / l0, i1 = 1.0f / l1;
    uint32_t* zh = (uint32_t*)(g_heap + ZS16);
    const int rowlo = r0 + wid * 16 + g;
#pragma unroll
    for (int n = 0; n < 16; n++) {
        const int col = h * 128 + n * 8 + qq * 2;
        zh[((size_t)rowlo * 2048 + col) >> 1] =
            pack_h2(zacc[n][0] * i0, zacc[n][1] * i0);
        zh[((size_t)(rowlo + 8) * 2048 + col) >> 1] =
            pack_h2(zacc[n][2] * i1, zacc[n][3] * i1);
    }
}

// ---------------------------------------------------------------------------
extern "C" void kernel_launch(void* const* d_in, const int* in_sizes, int n_in,
                              void* d_out, int out_size)
{
    const float* x     = (const float*)d_in[0];
    const float* q     = (const float*)d_in[1];
    const float* k     = (const float*)d_in[2];
    const float* v     = (const float*)d_in[3];
    const float* o     = (const float*)d_in[4];
    const float* theta = (const float*)d_in[5];
    float* out = (float*)d_out;

    cudaFuncSetAttribute(attn_hmma,
                         cudaFuncAttributeMaxDynamicSharedMemorySize, 176128);

    cvtx16s<<<8192, 256>>>(x);
    splitwT<<<dim3(64, 4, 16), dim3(32, 8)>>>(q);
    proj_v9<<<dim3(32, 16), 512>>>(x, QOFF);
    splitwT<<<dim3(64, 4, 16), dim3(32, 8)>>>(k);
    proj_v9<<<dim3(32, 16), 512>>>(x, KOFF);
    vproj16<<<dim3(32, 16), 512>>>(v);
    rope_pack<<<dim3(1024, 16, 2), 256>>>(theta);
    attn_hmma<<<512, 256, 176128>>>();
    outproj1p<<<dim3(32, 16), 512>>>(out, o);
}